// round 5
// baseline (speedup 1.0000x reference)
#include <cuda_runtime.h>
#include <cstdint>

#define BSZ 8192
#define DIM 128

#define GRAM_CTAS 64
#define GRAM_K    128                 // rows per gram CTA
#define YP 136                        // Y pitch (floats): conflict-free frag loads

#define QUAD_CTAS 128
#define QUAD_ROWS 64
#define XP 132                        // X pitch
#define GP 136                        // G pitch

#define TOTAL_CTAS (GRAM_CTAS + QUAD_CTAS)

#define GRAM_SMEM_BYTES (2 * GRAM_K * YP * 4)                       // 139264
#define QUAD_SMEM_BYTES (2 * QUAD_ROWS * XP * 4 + DIM * GP * 4 + 3 * 2 * QUAD_ROWS * 4 + QUAD_ROWS * 4)
#define FUSED_SMEM_BYTES (GRAM_SMEM_BYTES > QUAD_SMEM_BYTES ? GRAM_SMEM_BYTES : QUAD_SMEM_BYTES)

__device__ float g_gram_part[GRAM_CTAS][3][DIM][DIM];   // ~12.6 MB
__device__ float g_gram[3][DIM][DIM];
__device__ float g_loss_part[QUAD_CTAS];
__device__ int   g_ctr1, g_ctr2, g_ctr3;

// ---------------------------------------------------------------------------
__device__ __forceinline__ uint32_t to_tf32(float f) {
    uint32_t r;
    asm("cvt.rn.tf32.f32 %0, %1;" : "=r"(r) : "f"(f));
    return r;
}
// D(16x8) += A(16x8) * B(8x8), tf32, f32 accum (sm_80 baseline -> ok at compute_103)
__device__ __forceinline__ void mma_tf32(float* d, const uint32_t* a, uint32_t b0, uint32_t b1) {
    asm volatile(
        "mma.sync.aligned.m16n8k8.row.col.f32.tf32.tf32.f32 "
        "{%0,%1,%2,%3}, {%4,%5,%6,%7}, {%8,%9}, {%0,%1,%2,%3};"
        : "+f"(d[0]), "+f"(d[1]), "+f"(d[2]), "+f"(d[3])
        : "r"(a[0]), "r"(a[1]), "r"(a[2]), "r"(a[3]), "r"(b0), "r"(b1));
}
// spin until *ctr >= target (writers do __threadfence() before atomicAdd)
__device__ __forceinline__ void spin_wait(int* ctr, int target, int tid, int* sflag) {
    if (tid == 0) {
        while (*(volatile int*)ctr < target) __nanosleep(128);
        *sflag = 1;   // just a marker; sync below orders the block
    }
    __syncthreads();
    __threadfence();  // acquire: subsequent gmem reads see signalled data
}

// ============================================================================
// reset kernel: zero the cross-CTA counters (runs before the fused kernel)
// ============================================================================
__global__ void reset_kernel() {
    g_ctr1 = 0; g_ctr2 = 0; g_ctr3 = 0;
}

// ============================================================================
// fused kernel
//   CTA < 64:    gram role  (tf32 mma partial Grams of normalized Ys/Yt)
//   CTA >= 64:   quad role  (normalize X, reduce G slice, quad forms, loss)
// ============================================================================
__global__ void __launch_bounds__(256) fused_kernel(const float* __restrict__ zxs,
                                                    const float* __restrict__ zys,
                                                    const float* __restrict__ zxt,
                                                    const float* __restrict__ zyt,
                                                    float* __restrict__ out) {
    extern __shared__ char smraw[];
    const int tid  = threadIdx.x;
    const int wid  = tid >> 5;
    const int lane = tid & 31;
    const int gid  = lane >> 2;
    const int tg   = lane & 3;
    const int cta  = blockIdx.x;

    if (cta < GRAM_CTAS) {
        // ==================== GRAM ROLE ====================
        uint32_t* smg = (uint32_t*)smraw;
        uint32_t* sY[2] = {smg, smg + GRAM_K * YP};
        const int row0 = cta * GRAM_K;

#pragma unroll 1
        for (int which = 0; which < 2; which++) {
            const float* src = which ? zyt : zys;
            int r = tid >> 1, part = tid & 1;
            const float4* s = (const float4*)(src + (size_t)(row0 + r) * DIM) + part * 16;
            float4 v[16];
            float ss = 0.f;
#pragma unroll
            for (int i = 0; i < 16; i++) {
                v[i] = s[i];
                ss += v[i].x * v[i].x + v[i].y * v[i].y + v[i].z * v[i].z + v[i].w * v[i].w;
            }
            ss += __shfl_xor_sync(0xffffffffu, ss, 1);
            float inv = rsqrtf(fmaxf(ss, 1e-24f));
            uint32_t* d = sY[which] + (size_t)r * YP + part * 64;
#pragma unroll
            for (int i = 0; i < 16; i++) {
                uint4 t;
                t.x = to_tf32(v[i].x * inv);
                t.y = to_tf32(v[i].y * inv);
                t.z = to_tf32(v[i].z * inv);
                t.w = to_tf32(v[i].w * inv);
                *(uint4*)(d + i * 4) = t;
            }
        }
        __syncthreads();

        const int m0 = wid * 16;
#pragma unroll 1
        for (int m = 0; m < 3; m++) {
            const uint32_t* Ya = sY[m == 1 ? 1 : 0];
            const uint32_t* Yb = sY[m == 0 ? 0 : 1];
            float acc[16][4];
#pragma unroll
            for (int t = 0; t < 16; t++)
#pragma unroll
                for (int j = 0; j < 4; j++) acc[t][j] = 0.f;

#pragma unroll 2
            for (int k0 = 0; k0 < GRAM_K; k0 += 8) {
                uint32_t a[4];
                a[0] = Ya[(k0 + tg) * YP + m0 + gid];
                a[1] = Ya[(k0 + tg) * YP + m0 + 8 + gid];
                a[2] = Ya[(k0 + 4 + tg) * YP + m0 + gid];
                a[3] = Ya[(k0 + 4 + tg) * YP + m0 + 8 + gid];
#pragma unroll
                for (int t = 0; t < 16; t++) {
                    uint32_t b0 = Yb[(k0 + tg) * YP + t * 8 + gid];
                    uint32_t b1 = Yb[(k0 + 4 + tg) * YP + t * 8 + gid];
                    mma_tf32(acc[t], a, b0, b1);
                }
            }

            float* dst = &g_gram_part[cta][m][0][0];
            int r1 = m0 + gid, r2 = m0 + 8 + gid;
#pragma unroll
            for (int t = 0; t < 16; t++) {
                *(float2*)(dst + r1 * DIM + t * 8 + 2 * tg) = make_float2(acc[t][0], acc[t][1]);
                *(float2*)(dst + r2 * DIM + t * 8 + 2 * tg) = make_float2(acc[t][2], acc[t][3]);
            }
        }
        // signal partials complete
        __syncthreads();
        if (tid == 0) {
            __threadfence();
            atomicAdd(&g_ctr1, 1);
        }
        return;
    }

    // ==================== QUAD ROLE ====================
    const int qb = cta - GRAM_CTAS;                  // 0..127
    float* smq = (float*)smraw;
    float* sX[2] = {smq, smq + QUAD_ROWS * XP};
    uint32_t* sG = (uint32_t*)(smq + 2 * QUAD_ROWS * XP);
    float* sP = smq + 2 * QUAD_ROWS * XP + DIM * GP;  // [3][2][64]
    float* sCos = sP + 3 * 2 * QUAD_ROWS;             // [64]
    __shared__ int sflag;
    __shared__ int sLast;

    const int row0 = qb * QUAD_ROWS;

    // load + normalize X (overlaps with gram CTAs running elsewhere)
#pragma unroll 1
    for (int which = 0; which < 2; which++) {
        const float* src = which ? zxt : zxs;
        int r = tid >> 2, part = tid & 3;
        const float4* s = (const float4*)(src + (size_t)(row0 + r) * DIM) + part * 8;
        float4 v[8];
        float ss = 0.f;
#pragma unroll
        for (int i = 0; i < 8; i++) {
            v[i] = s[i];
            ss += v[i].x * v[i].x + v[i].y * v[i].y + v[i].z * v[i].z + v[i].w * v[i].w;
        }
        ss += __shfl_xor_sync(0xffffffffu, ss, 1);
        ss += __shfl_xor_sync(0xffffffffu, ss, 2);
        float inv = rsqrtf(fmaxf(ss, 1e-24f));
        float4* d = (float4*)(sX[which] + (size_t)r * XP + part * 32);
#pragma unroll
        for (int i = 0; i < 8; i++) {
            v[i].x *= inv; v[i].y *= inv; v[i].z *= inv; v[i].w *= inv;
            d[i] = v[i];
        }
    }

    // wait for all gram partials, then reduce this CTA's 384-element slice
    spin_wait(&g_ctr1, GRAM_CTAS, tid, &sflag);
    {
        const float* base = &g_gram_part[0][0][0][0];
        int e1 = qb * 384 + tid;          // 256 elems
        int e2 = qb * 384 + 256 + tid;    // 128 elems (tid<128)
        float s1 = 0.f, s2 = 0.f;
#pragma unroll 8
        for (int p = 0; p < GRAM_CTAS; p++) {
            const float* bp = base + (size_t)p * (3 * DIM * DIM);
            s1 += bp[e1];
            if (tid < 128) s2 += bp[e2];
        }
        (&g_gram[0][0][0])[e1] = s1;
        if (tid < 128) (&g_gram[0][0][0])[e2] = s2;
    }
    __syncthreads();
    if (tid == 0) {
        __threadfence();
        atomicAdd(&g_ctr2, 1);
    }
    spin_wait(&g_ctr2, QUAD_CTAS, tid, &sflag);

    const int m0 = (wid & 3) * 16;
    const int nh = wid >> 2;

#pragma unroll 1
    for (int m = 0; m < 3; m++) {
        if (m) __syncthreads();          // prior-mat sG reads done
        // stage G[m] as tf32, pitch GP
        {
            const float4* gsrc = (const float4*)&g_gram[m][0][0];
#pragma unroll
            for (int i = 0; i < 16; i++) {
                int idx = tid + i * 256;
                float4 g = gsrc[idx];
                int rrow = idx >> 5;
                int rcol = (idx & 31) * 4;
                uint4 t;
                t.x = to_tf32(g.x); t.y = to_tf32(g.y);
                t.z = to_tf32(g.z); t.w = to_tf32(g.w);
                *(uint4*)(sG + rrow * GP + rcol) = t;
            }
        }
        __syncthreads();

        const float* Xa = sX[m == 1 ? 1 : 0];
        const float* Xb = sX[m == 0 ? 0 : 1];

        float acc[8][4];
#pragma unroll
        for (int t = 0; t < 8; t++)
#pragma unroll
            for (int j = 0; j < 4; j++) acc[t][j] = 0.f;

#pragma unroll 2
        for (int k0 = 0; k0 < DIM; k0 += 8) {
            uint32_t a[4];
            a[0] = to_tf32(Xa[(m0 + gid) * XP + k0 + tg]);
            a[1] = to_tf32(Xa[(m0 + 8 + gid) * XP + k0 + tg]);
            a[2] = to_tf32(Xa[(m0 + gid) * XP + k0 + 4 + tg]);
            a[3] = to_tf32(Xa[(m0 + 8 + gid) * XP + k0 + 4 + tg]);
#pragma unroll
            for (int t = 0; t < 8; t++) {
                int n0 = nh * 64 + t * 8;
                uint32_t b0 = sG[(k0 + tg) * GP + n0 + gid];
                uint32_t b1 = sG[(k0 + 4 + tg) * GP + n0 + gid];
                mma_tf32(acc[t], a, b0, b1);
            }
        }

        float p1 = 0.f, p2 = 0.f;
#pragma unroll
        for (int t = 0; t < 8; t++) {
            int n0 = nh * 64 + t * 8;
            float2 x1 = *(const float2*)(Xb + (m0 + gid) * XP + n0 + 2 * tg);
            float2 x2 = *(const float2*)(Xb + (m0 + 8 + gid) * XP + n0 + 2 * tg);
            p1 += acc[t][0] * x1.x + acc[t][1] * x1.y;
            p2 += acc[t][2] * x2.x + acc[t][3] * x2.y;
        }
        p1 += __shfl_xor_sync(0xffffffffu, p1, 1);
        p1 += __shfl_xor_sync(0xffffffffu, p1, 2);
        p2 += __shfl_xor_sync(0xffffffffu, p2, 1);
        p2 += __shfl_xor_sync(0xffffffffu, p2, 2);
        if (tg == 0) {
            sP[(m * 2 + nh) * QUAD_ROWS + m0 + gid]     = p1;
            sP[(m * 2 + nh) * QUAD_ROWS + m0 + 8 + gid] = p2;
        }
    }
    __syncthreads();

    if (tid < QUAD_ROWS) {
        float A = sP[0 * QUAD_ROWS + tid] + sP[1 * QUAD_ROWS + tid];
        float B = sP[2 * QUAD_ROWS + tid] + sP[3 * QUAD_ROWS + tid];
        float C = sP[4 * QUAD_ROWS + tid] + sP[5 * QUAD_ROWS + tid];
        sCos[tid] = C * rsqrtf(fmaxf(A * B, 1e-30f));
    }
    __syncthreads();
    if (tid == 0) {
        float s = 0.f;
#pragma unroll 8
        for (int i = 0; i < QUAD_ROWS; i++) s += sCos[i];
        g_loss_part[qb] = s;
        __threadfence();
        int v = atomicAdd(&g_ctr3, 1);
        sLast = (v == QUAD_CTAS - 1);
    }
    __syncthreads();

    // last CTA: fixed-order final reduction -> scalar loss
    if (sLast) {
        __threadfence();
        __shared__ float w[4];
        if (tid < QUAD_CTAS) {
            float v = g_loss_part[tid];
#pragma unroll
            for (int off = 16; off > 0; off >>= 1)
                v += __shfl_xor_sync(0xffffffffu, v, off);
            if ((tid & 31) == 0) w[tid >> 5] = v;
        }
        __syncthreads();
        if (tid == 0) {
            float s = w[0] + w[1] + w[2] + w[3];
            const float b = (float)BSZ;
            out[0] = (2.f * b - 2.f * s) / (b * b);
        }
    }
}

// ============================================================================
extern "C" void kernel_launch(void* const* d_in, const int* in_sizes, int n_in,
                              void* d_out, int out_size) {
    (void)in_sizes; (void)n_in; (void)out_size;
    const float* zxs = (const float*)d_in[0];
    const float* zys = (const float*)d_in[1];
    const float* zxt = (const float*)d_in[2];
    const float* zyt = (const float*)d_in[3];
    // temperature (d_in[4]) cancels exactly under row-normalization.

    cudaFuncSetAttribute(fused_kernel, cudaFuncAttributeMaxDynamicSharedMemorySize,
                         FUSED_SMEM_BYTES);

    reset_kernel<<<1, 1>>>();
    fused_kernel<<<TOTAL_CTAS, 256, FUSED_SMEM_BYTES>>>(zxs, zys, zxt, zyt, (float*)d_out);
}

// round 6
// speedup vs baseline: 1.5091x; 1.5091x over previous
#include <cuda_runtime.h>
#include <cstdint>

#define BSZ 8192
#define DIM 128

#define NCTA 128          // one wave: 128 <= 148 SMs, 1 CTA/SM
#define ROWS 64           // rows of each tensor per CTA (128*64 = 8192)
#define NTHR 512

#define XP 132            // X pitch (floats): conflict-free A-frag loads
#define YP 136            // Y/G pitch: conflict-free B-frag loads

// smem layout (bytes):
//   sX   : 2 * 64 * XP * 4 = 67584   (fp32 normalized xs, xt — resident)
//   sYG  : 2 * 64 * YP * 4 = 69632   (tf32 Y tiles; reused as G[128][YP] stage)
//   sP   : 3*4*64*4 = 3072, sCos: 256
#define SM_X_FLOATS (2 * ROWS * XP)
#define SM_YG_U32   (2 * ROWS * YP)          // == 128*YP for G stage
#define SM_P_OFF    (SM_X_FLOATS + SM_YG_U32)
#define FUSED_SMEM_BYTES ((SM_P_OFF + 3 * 4 * ROWS + ROWS) * 4)

__device__ float    g_gram_part[NCTA][3][DIM][DIM];   // ~25 MB partials
__device__ uint32_t g_gram[3][DIM][DIM];              // tf32 bits
__device__ float    g_loss_part[NCTA];
__device__ int      g_ctr1, g_ctr2, g_ctr3;

// ---------------------------------------------------------------------------
__device__ __forceinline__ uint32_t to_tf32(float f) {
    uint32_t r;
    asm("cvt.rn.tf32.f32 %0, %1;" : "=r"(r) : "f"(f));
    return r;
}
__device__ __forceinline__ void mma_tf32(float* d, const uint32_t* a, uint32_t b0, uint32_t b1) {
    asm volatile(
        "mma.sync.aligned.m16n8k8.row.col.f32.tf32.tf32.f32 "
        "{%0,%1,%2,%3}, {%4,%5,%6,%7}, {%8,%9}, {%0,%1,%2,%3};"
        : "+f"(d[0]), "+f"(d[1]), "+f"(d[2]), "+f"(d[3])
        : "r"(a[0]), "r"(a[1]), "r"(a[2]), "r"(a[3]), "r"(b0), "r"(b1));
}
__device__ __forceinline__ void grid_wait(int* ctr, int target, int tid) {
    __syncthreads();
    if (tid == 0) {
        __threadfence();
        atomicAdd(ctr, 1);
        while (*(volatile int*)ctr < target) __nanosleep(64);
    }
    __syncthreads();
    __threadfence();   // acquire
}

__global__ void reset_kernel() { g_ctr1 = 0; g_ctr2 = 0; g_ctr3 = 0; }

// ============================================================================
__global__ void __launch_bounds__(NTHR) fused_kernel(const float* __restrict__ zxs,
                                                     const float* __restrict__ zys,
                                                     const float* __restrict__ zxt,
                                                     const float* __restrict__ zyt,
                                                     float* __restrict__ out) {
    extern __shared__ float smem[];
    float*    sX  = smem;                                  // [2][64][XP] fp32
    uint32_t* sY  = (uint32_t*)(smem + SM_X_FLOATS);       // [2][64][YP] tf32
    uint32_t* sG  = sY;                                    // union: [128][YP] tf32
    float*    sP  = smem + SM_P_OFF;                       // [3][4][64]
    float*    sCos = sP + 3 * 4 * ROWS;                    // [64]
    __shared__ int sLast;

    const int tid  = threadIdx.x;
    const int wid  = tid >> 5;
    const int lane = tid & 31;
    const int gid  = lane >> 2;
    const int tg   = lane & 3;
    const int cta  = blockIdx.x;
    const int row0 = cta * ROWS;

    // ---- phase 0: load + normalize (8 threads/row, 16 floats each) ----
    {
        int r = tid >> 3, part = tid & 7;
        // X (fp32, keep resident)
#pragma unroll 1
        for (int which = 0; which < 2; which++) {
            const float* src = which ? zxt : zxs;
            const float4* s = (const float4*)(src + (size_t)(row0 + r) * DIM) + part * 4;
            float4 v[4];
            float ss = 0.f;
#pragma unroll
            for (int i = 0; i < 4; i++) {
                v[i] = s[i];
                ss += v[i].x * v[i].x + v[i].y * v[i].y + v[i].z * v[i].z + v[i].w * v[i].w;
            }
            ss += __shfl_xor_sync(0xffffffffu, ss, 1);
            ss += __shfl_xor_sync(0xffffffffu, ss, 2);
            ss += __shfl_xor_sync(0xffffffffu, ss, 4);
            float inv = rsqrtf(fmaxf(ss, 1e-24f));
            float4* d = (float4*)(sX + (size_t)(which * ROWS + r) * XP + part * 16);
#pragma unroll
            for (int i = 0; i < 4; i++) {
                v[i].x *= inv; v[i].y *= inv; v[i].z *= inv; v[i].w *= inv;
                d[i] = v[i];
            }
        }
        // Y (tf32 bits)
#pragma unroll 1
        for (int which = 0; which < 2; which++) {
            const float* src = which ? zyt : zys;
            const float4* s = (const float4*)(src + (size_t)(row0 + r) * DIM) + part * 4;
            float4 v[4];
            float ss = 0.f;
#pragma unroll
            for (int i = 0; i < 4; i++) {
                v[i] = s[i];
                ss += v[i].x * v[i].x + v[i].y * v[i].y + v[i].z * v[i].z + v[i].w * v[i].w;
            }
            ss += __shfl_xor_sync(0xffffffffu, ss, 1);
            ss += __shfl_xor_sync(0xffffffffu, ss, 2);
            ss += __shfl_xor_sync(0xffffffffu, ss, 4);
            float inv = rsqrtf(fmaxf(ss, 1e-24f));
            uint32_t* d = sY + (size_t)(which * ROWS + r) * YP + part * 16;
#pragma unroll
            for (int i = 0; i < 4; i++) {
                uint4 t;
                t.x = to_tf32(v[i].x * inv);
                t.y = to_tf32(v[i].y * inv);
                t.z = to_tf32(v[i].z * inv);
                t.w = to_tf32(v[i].w * inv);
                *(uint4*)(d + i * 4) = t;
            }
        }
    }
    __syncthreads();

    // ---- phase 1: gram partials via mma (K=64).
    // warp w: m-strip (w&7)*16, n-half (w>>3)*64  -> 8 n-tiles each
    {
        const int m0 = (wid & 7) * 16;
        const int nh = wid >> 3;
#pragma unroll 1
        for (int m = 0; m < 3; m++) {
            const uint32_t* Ya = sY + (m == 1 ? ROWS * YP : 0);
            const uint32_t* Yb = sY + (m == 0 ? 0 : ROWS * YP);
            float acc[8][4];
#pragma unroll
            for (int t = 0; t < 8; t++)
#pragma unroll
                for (int j = 0; j < 4; j++) acc[t][j] = 0.f;

#pragma unroll 2
            for (int k0 = 0; k0 < ROWS; k0 += 8) {
                uint32_t a[4];
                a[0] = Ya[(k0 + tg) * YP + m0 + gid];
                a[1] = Ya[(k0 + tg) * YP + m0 + 8 + gid];
                a[2] = Ya[(k0 + 4 + tg) * YP + m0 + gid];
                a[3] = Ya[(k0 + 4 + tg) * YP + m0 + 8 + gid];
#pragma unroll
                for (int t = 0; t < 8; t++) {
                    int n0 = nh * 64 + t * 8;
                    uint32_t b0 = Yb[(k0 + tg) * YP + n0 + gid];
                    uint32_t b1 = Yb[(k0 + 4 + tg) * YP + n0 + gid];
                    mma_tf32(acc[t], a, b0, b1);
                }
            }
            float* dst = &g_gram_part[cta][m][0][0];
            int r1 = m0 + gid, r2 = m0 + 8 + gid;
#pragma unroll
            for (int t = 0; t < 8; t++) {
                int n0 = nh * 64 + t * 8;
                *(float2*)(dst + r1 * DIM + n0 + 2 * tg) = make_float2(acc[t][0], acc[t][1]);
                *(float2*)(dst + r2 * DIM + n0 + 2 * tg) = make_float2(acc[t][2], acc[t][3]);
            }
        }
    }

    // ---- barrier 1: all partials visible ----
    grid_wait(&g_ctr1, NCTA, tid);

    // ---- phase 2: reduce G slice (fixed order), store tf32 bits ----
    if (tid < 384) {
        int e = cta * 384 + tid;
        const float* base = &g_gram_part[0][0][0][0];
        float s = 0.f;
#pragma unroll 16
        for (int p = 0; p < NCTA; p++)
            s += base[(size_t)p * (3 * DIM * DIM) + e];
        (&g_gram[0][0][0])[e] = to_tf32(s);
    }

    // ---- barrier 2: full G available ----
    grid_wait(&g_ctr2, NCTA, tid);

    // ---- phase 3: quadratic forms via mma.
    // warp w: m-strip (w&3)*16, n-quarter (w>>2)*32 -> 4 n-tiles each
    {
        const int m0 = (wid & 3) * 16;
        const int nq = wid >> 2;
#pragma unroll 1
        for (int m = 0; m < 3; m++) {
            if (m) __syncthreads();
            // stage G[m] (raw tf32 copy): 4096 uint4 / 512 threads = 8 each
            {
                const uint4* gsrc = (const uint4*)&g_gram[m][0][0];
#pragma unroll
                for (int i = 0; i < 8; i++) {
                    int idx = tid + i * NTHR;
                    uint4 g = gsrc[idx];
                    int rrow = idx >> 5;
                    int rcol = (idx & 31) * 4;
                    *(uint4*)(sG + rrow * YP + rcol) = g;
                }
            }
            __syncthreads();

            const float* Xa = sX + (m == 1 ? ROWS * XP : 0);
            const float* Xb = sX + (m == 0 ? 0 : ROWS * XP);

            float acc[4][4];
#pragma unroll
            for (int t = 0; t < 4; t++)
#pragma unroll
                for (int j = 0; j < 4; j++) acc[t][j] = 0.f;

#pragma unroll 2
            for (int k0 = 0; k0 < DIM; k0 += 8) {
                uint32_t a[4];
                a[0] = to_tf32(Xa[(m0 + gid) * XP + k0 + tg]);
                a[1] = to_tf32(Xa[(m0 + 8 + gid) * XP + k0 + tg]);
                a[2] = to_tf32(Xa[(m0 + gid) * XP + k0 + 4 + tg]);
                a[3] = to_tf32(Xa[(m0 + 8 + gid) * XP + k0 + 4 + tg]);
#pragma unroll
                for (int t = 0; t < 4; t++) {
                    int n0 = nq * 32 + t * 8;
                    uint32_t b0 = sG[(k0 + tg) * YP + n0 + gid];
                    uint32_t b1 = sG[(k0 + 4 + tg) * YP + n0 + gid];
                    mma_tf32(acc[t], a, b0, b1);
                }
            }

            float p1 = 0.f, p2 = 0.f;
#pragma unroll
            for (int t = 0; t < 4; t++) {
                int n0 = nq * 32 + t * 8;
                float2 x1 = *(const float2*)(Xb + (m0 + gid) * XP + n0 + 2 * tg);
                float2 x2 = *(const float2*)(Xb + (m0 + 8 + gid) * XP + n0 + 2 * tg);
                p1 += acc[t][0] * x1.x + acc[t][1] * x1.y;
                p2 += acc[t][2] * x2.x + acc[t][3] * x2.y;
            }
            p1 += __shfl_xor_sync(0xffffffffu, p1, 1);
            p1 += __shfl_xor_sync(0xffffffffu, p1, 2);
            p2 += __shfl_xor_sync(0xffffffffu, p2, 1);
            p2 += __shfl_xor_sync(0xffffffffu, p2, 2);
            if (tg == 0) {
                sP[(m * 4 + nq) * ROWS + m0 + gid]     = p1;
                sP[(m * 4 + nq) * ROWS + m0 + 8 + gid] = p2;
            }
        }
    }
    __syncthreads();

    // ---- cosines + per-CTA partial ----
    if (tid < ROWS) {
        float A = sP[0 * ROWS + tid] + sP[1 * ROWS + tid] + sP[2 * ROWS + tid] + sP[3 * ROWS + tid];
        float B = sP[4 * ROWS + tid] + sP[5 * ROWS + tid] + sP[6 * ROWS + tid] + sP[7 * ROWS + tid];
        float C = sP[8 * ROWS + tid] + sP[9 * ROWS + tid] + sP[10 * ROWS + tid] + sP[11 * ROWS + tid];
        sCos[tid] = C * rsqrtf(fmaxf(A * B, 1e-30f));
    }
    __syncthreads();
    if (tid == 0) {
        float s = 0.f;
#pragma unroll 8
        for (int i = 0; i < ROWS; i++) s += sCos[i];
        g_loss_part[cta] = s;
        __threadfence();
        int v = atomicAdd(&g_ctr3, 1);
        sLast = (v == NCTA - 1);
    }
    __syncthreads();

    // ---- last CTA: fixed-order final reduction -> scalar loss ----
    if (sLast) {
        __threadfence();
        __shared__ float w[4];
        if (tid < NCTA) {
            float v = g_loss_part[tid];
#pragma unroll
            for (int off = 16; off > 0; off >>= 1)
                v += __shfl_xor_sync(0xffffffffu, v, off);
            if ((tid & 31) == 0) w[tid >> 5] = v;
        }
        __syncthreads();
        if (tid == 0) {
            float s = w[0] + w[1] + w[2] + w[3];
            const float b = (float)BSZ;
            out[0] = (2.f * b - 2.f * s) / (b * b);
        }
    }
}

// ============================================================================
extern "C" void kernel_launch(void* const* d_in, const int* in_sizes, int n_in,
                              void* d_out, int out_size) {
    (void)in_sizes; (void)n_in; (void)out_size;
    const float* zxs = (const float*)d_in[0];
    const float* zys = (const float*)d_in[1];
    const float* zxt = (const float*)d_in[2];
    const float* zyt = (const float*)d_in[3];
    // temperature (d_in[4]) cancels exactly under row-normalization.

    cudaFuncSetAttribute(fused_kernel, cudaFuncAttributeMaxDynamicSharedMemorySize,
                         FUSED_SMEM_BYTES);

    reset_kernel<<<1, 1>>>();
    fused_kernel<<<NCTA, NTHR, FUSED_SMEM_BYTES>>>(zxs, zys, zxt, zyt, (float*)d_out);
}

// round 7
// speedup vs baseline: 1.5897x; 1.0534x over previous
#include <cuda_runtime.h>
#include <cstdint>

#define BSZ 8192
#define DIM 128

#define NCTA 128          // one wave: 128 <= 148 SMs, 1 CTA/SM (grid-sync safe)
#define ROWS 64           // rows of each tensor per CTA
#define NTHR 512

#define XP 132            // X pitch (floats): conflict-free A-frag loads
#define YP 136            // Y/G pitch: conflict-free B-frag loads

// smem (floats): sX 2*64*XP=16896 | bufA 128*YP=17408 (also Y tiles) |
//                bufB 17408 | sP 12*64=768 | sCos 64   => 210176 bytes
#define SM_X_FLOATS (2 * ROWS * XP)
#define SM_BUFA_OFF SM_X_FLOATS
#define SM_BUFB_OFF (SM_BUFA_OFF + DIM * YP)
#define SM_P_OFF    (SM_BUFB_OFF + DIM * YP)
#define FUSED_SMEM_BYTES ((SM_P_OFF + 12 * ROWS + ROWS) * 4)

__device__ float    g_gram_part[NCTA][3][DIM][DIM];   // ~25 MB (L2-resident)
__device__ uint32_t g_gram[3][DIM][DIM];              // tf32 bits
__device__ float    g_loss_part[NCTA];
__device__ int      g_ctr1, g_ctr2, g_ctr3;

// ---------------------------------------------------------------------------
__device__ __forceinline__ uint32_t to_tf32(float f) {
    uint32_t r;
    asm("cvt.rn.tf32.f32 %0, %1;" : "=r"(r) : "f"(f));
    return r;
}
__device__ __forceinline__ void mma_tf32(float* d, const uint32_t* a, uint32_t b0, uint32_t b1) {
    asm volatile(
        "mma.sync.aligned.m16n8k8.row.col.f32.tf32.tf32.f32 "
        "{%0,%1,%2,%3}, {%4,%5,%6,%7}, {%8,%9}, {%0,%1,%2,%3};"
        : "+f"(d[0]), "+f"(d[1]), "+f"(d[2]), "+f"(d[3])
        : "r"(a[0]), "r"(a[1]), "r"(a[2]), "r"(a[3]), "r"(b0), "r"(b1));
}
__device__ __forceinline__ uint32_t smem_u32(const void* p) {
    uint32_t a;
    asm("{ .reg .u64 t; cvta.to.shared.u64 t, %1; cvt.u32.u64 %0, t; }" : "=r"(a) : "l"(p));
    return a;
}
__device__ __forceinline__ void cp16(uint32_t dst, const void* src) {
    asm volatile("cp.async.cg.shared.global [%0], [%1], 16;" :: "r"(dst), "l"(src));
}
#define CP_COMMIT() asm volatile("cp.async.commit_group;" ::: "memory")
#define CP_WAIT(n)  asm volatile("cp.async.wait_group %0;" :: "n"(n) : "memory")

// arrive: make this block's gmem writes visible, bump counter (no wait)
__device__ __forceinline__ void grid_arrive(int* ctr, int tid) {
    __threadfence();
    __syncthreads();
    if (tid == 0) atomicAdd(ctr, 1);
}
// wait: spin until all arrived, then acquire
__device__ __forceinline__ void grid_spin(int* ctr, int target, int tid) {
    if (tid == 0) {
        while (*(volatile int*)ctr < target) __nanosleep(32);
    }
    __syncthreads();
    __threadfence();
}

__global__ void reset_kernel() { g_ctr1 = 0; g_ctr2 = 0; g_ctr3 = 0; }

// ============================================================================
__global__ void __launch_bounds__(NTHR) fused_kernel(const float* __restrict__ zxs,
                                                     const float* __restrict__ zys,
                                                     const float* __restrict__ zxt,
                                                     const float* __restrict__ zyt,
                                                     float* __restrict__ out) {
    extern __shared__ float smem[];
    float*    sX   = smem;                               // [2][64][XP] fp32
    uint32_t* sY   = (uint32_t*)(smem + SM_BUFA_OFF);    // [2][64][YP] tf32 (phase 0/1)
    uint32_t* bufA = sY;                                 // [128][YP] (phase 3)
    uint32_t* bufB = (uint32_t*)(smem + SM_BUFB_OFF);    // [128][YP]
    float*    sP   = smem + SM_P_OFF;                    // [3][4][64]
    float*    sCos = sP + 12 * ROWS;                     // [64]
    __shared__ int sLast;

    const int tid  = threadIdx.x;
    const int wid  = tid >> 5;
    const int lane = tid & 31;
    const int gid  = lane >> 2;
    const int tg   = lane & 3;
    const int cta  = blockIdx.x;
    const int row0 = cta * ROWS;

    // ---- phase 0: load + normalize Y (8 threads/row, 16 floats each) ----
    {
        int r = tid >> 3, part = tid & 7;
#pragma unroll 1
        for (int which = 0; which < 2; which++) {
            const float* src = which ? zyt : zys;
            const float4* s = (const float4*)(src + (size_t)(row0 + r) * DIM) + part * 4;
            float4 v[4];
            float ss = 0.f;
#pragma unroll
            for (int i = 0; i < 4; i++) {
                v[i] = s[i];
                ss += v[i].x * v[i].x + v[i].y * v[i].y + v[i].z * v[i].z + v[i].w * v[i].w;
            }
            ss += __shfl_xor_sync(0xffffffffu, ss, 1);
            ss += __shfl_xor_sync(0xffffffffu, ss, 2);
            ss += __shfl_xor_sync(0xffffffffu, ss, 4);
            float inv = rsqrtf(fmaxf(ss, 1e-24f));
            uint32_t* d = sY + (size_t)(which * ROWS + r) * YP + part * 16;
#pragma unroll
            for (int i = 0; i < 4; i++) {
                uint4 t;
                t.x = to_tf32(v[i].x * inv);
                t.y = to_tf32(v[i].y * inv);
                t.z = to_tf32(v[i].z * inv);
                t.w = to_tf32(v[i].w * inv);
                *(uint4*)(d + i * 4) = t;
            }
        }
    }
    __syncthreads();

    // ---- phase 1: gram partials via mma (K=64), warp tile 32x32 ----
    {
        const int m0  = (wid & 3) * 32;
        const int n0q = (wid >> 2) * 32;
#pragma unroll 1
        for (int m = 0; m < 3; m++) {
            const uint32_t* Ya = sY + (m == 1 ? ROWS * YP : 0);
            const uint32_t* Yb = sY + (m == 0 ? 0 : ROWS * YP);
            float acc[8][4];
#pragma unroll
            for (int t = 0; t < 8; t++)
#pragma unroll
                for (int j = 0; j < 4; j++) acc[t][j] = 0.f;

#pragma unroll 2
            for (int k0 = 0; k0 < ROWS; k0 += 8) {
                uint32_t a[8];
#pragma unroll
                for (int mt = 0; mt < 2; mt++) {
                    int mb = m0 + mt * 16;
                    a[mt * 4 + 0] = Ya[(k0 + tg) * YP + mb + gid];
                    a[mt * 4 + 1] = Ya[(k0 + tg) * YP + mb + 8 + gid];
                    a[mt * 4 + 2] = Ya[(k0 + 4 + tg) * YP + mb + gid];
                    a[mt * 4 + 3] = Ya[(k0 + 4 + tg) * YP + mb + 8 + gid];
                }
                uint32_t bs[4][2];
#pragma unroll
                for (int t = 0; t < 4; t++) {
                    int n0 = n0q + t * 8;
                    bs[t][0] = Yb[(k0 + tg) * YP + n0 + gid];
                    bs[t][1] = Yb[(k0 + 4 + tg) * YP + n0 + gid];
                }
#pragma unroll
                for (int mt = 0; mt < 2; mt++)
#pragma unroll
                    for (int t = 0; t < 4; t++)
                        mma_tf32(acc[mt * 4 + t], a + mt * 4, bs[t][0], bs[t][1]);
            }
            float* dst = &g_gram_part[cta][m][0][0];
#pragma unroll
            for (int mt = 0; mt < 2; mt++) {
                int r1 = m0 + mt * 16 + gid, r2 = r1 + 8;
#pragma unroll
                for (int t = 0; t < 4; t++) {
                    int n0 = n0q + t * 8;
                    *(float2*)(dst + r1 * DIM + n0 + 2 * tg) =
                        make_float2(acc[mt * 4 + t][0], acc[mt * 4 + t][1]);
                    *(float2*)(dst + r2 * DIM + n0 + 2 * tg) =
                        make_float2(acc[mt * 4 + t][2], acc[mt * 4 + t][3]);
                }
            }
        }
    }

    // ---- arrive barrier 1, then hide the X load in the wait ----
    grid_arrive(&g_ctr1, tid);
    {
        int r = tid >> 3, part = tid & 7;
#pragma unroll 1
        for (int which = 0; which < 2; which++) {
            const float* src = which ? zxt : zxs;
            const float4* s = (const float4*)(src + (size_t)(row0 + r) * DIM) + part * 4;
            float4 v[4];
            float ss = 0.f;
#pragma unroll
            for (int i = 0; i < 4; i++) {
                v[i] = s[i];
                ss += v[i].x * v[i].x + v[i].y * v[i].y + v[i].z * v[i].z + v[i].w * v[i].w;
            }
            ss += __shfl_xor_sync(0xffffffffu, ss, 1);
            ss += __shfl_xor_sync(0xffffffffu, ss, 2);
            ss += __shfl_xor_sync(0xffffffffu, ss, 4);
            float inv = rsqrtf(fmaxf(ss, 1e-24f));
            float4* d = (float4*)(sX + (size_t)(which * ROWS + r) * XP + part * 16);
#pragma unroll
            for (int i = 0; i < 4; i++) {
                v[i].x *= inv; v[i].y *= inv; v[i].z *= inv; v[i].w *= inv;
                d[i] = v[i];
            }
        }
    }
    grid_spin(&g_ctr1, NCTA, tid);

    // ---- phase 2: reduce G slice (fixed order), store tf32 bits ----
    if (tid < 384) {
        int e = cta * 384 + tid;
        const float* base = &g_gram_part[0][0][0][0];
        float s = 0.f;
#pragma unroll 16
        for (int p = 0; p < NCTA; p++)
            s += base[(size_t)p * (3 * DIM * DIM) + e];
        (&g_gram[0][0][0])[e] = to_tf32(s);
    }
    grid_arrive(&g_ctr2, tid);
    grid_spin(&g_ctr2, NCTA, tid);

    // ---- phase 3: quadratic forms; cp.async double-buffered G staging ----
    {
        const uint32_t bA = smem_u32(bufA);
        const uint32_t bB = smem_u32(bufB);
        // stage helper inline: 4096 float4 / 512 thr = 8 cp.async each
        auto stage = [&](uint32_t dstb, const uint32_t* gsrc) {
#pragma unroll
            for (int i = 0; i < 8; i++) {
                int idx = tid + i * NTHR;
                int rrow = idx >> 5;
                int rcol = (idx & 31) * 4;
                cp16(dstb + (uint32_t)(rrow * YP + rcol) * 4, gsrc + idx * 4);
            }
        };
        stage(bA, &g_gram[0][0][0]); CP_COMMIT();
        stage(bB, &g_gram[1][0][0]); CP_COMMIT();

        const int m0 = (wid & 3) * 16;
        const int nq = wid >> 2;

#pragma unroll 1
        for (int m = 0; m < 3; m++) {
            if (m == 1) { stage(bA, &g_gram[2][0][0]); CP_COMMIT(); CP_WAIT(1); }
            else if (m == 0) CP_WAIT(1);
            else CP_WAIT(0);
            __syncthreads();

            const uint32_t* sG = (m == 1) ? bufB : bufA;
            const float* Xa = sX + (m == 1 ? ROWS * XP : 0);
            const float* Xb = sX + (m == 0 ? 0 : ROWS * XP);

            float acc[4][4];
#pragma unroll
            for (int t = 0; t < 4; t++)
#pragma unroll
                for (int j = 0; j < 4; j++) acc[t][j] = 0.f;

#pragma unroll 2
            for (int k0 = 0; k0 < DIM; k0 += 8) {
                uint32_t a[4];
                a[0] = to_tf32(Xa[(m0 + gid) * XP + k0 + tg]);
                a[1] = to_tf32(Xa[(m0 + 8 + gid) * XP + k0 + tg]);
                a[2] = to_tf32(Xa[(m0 + gid) * XP + k0 + 4 + tg]);
                a[3] = to_tf32(Xa[(m0 + 8 + gid) * XP + k0 + 4 + tg]);
#pragma unroll
                for (int t = 0; t < 4; t++) {
                    int n0 = nq * 32 + t * 8;
                    uint32_t b0 = sG[(k0 + tg) * YP + n0 + gid];
                    uint32_t b1 = sG[(k0 + 4 + tg) * YP + n0 + gid];
                    mma_tf32(acc[t], a, b0, b1);
                }
            }

            float p1 = 0.f, p2 = 0.f;
#pragma unroll
            for (int t = 0; t < 4; t++) {
                int n0 = nq * 32 + t * 8;
                float2 x1 = *(const float2*)(Xb + (m0 + gid) * XP + n0 + 2 * tg);
                float2 x2 = *(const float2*)(Xb + (m0 + 8 + gid) * XP + n0 + 2 * tg);
                p1 += acc[t][0] * x1.x + acc[t][1] * x1.y;
                p2 += acc[t][2] * x2.x + acc[t][3] * x2.y;
            }
            p1 += __shfl_xor_sync(0xffffffffu, p1, 1);
            p1 += __shfl_xor_sync(0xffffffffu, p1, 2);
            p2 += __shfl_xor_sync(0xffffffffu, p2, 1);
            p2 += __shfl_xor_sync(0xffffffffu, p2, 2);
            if (tg == 0) {
                sP[(m * 4 + nq) * ROWS + m0 + gid]     = p1;
                sP[(m * 4 + nq) * ROWS + m0 + 8 + gid] = p2;
            }
            __syncthreads();   // all reads of current buffer done before reuse
        }
    }

    // ---- cosines + per-CTA partial ----
    if (tid < ROWS) {
        float A = sP[0 * ROWS + tid] + sP[1 * ROWS + tid] + sP[2 * ROWS + tid] + sP[3 * ROWS + tid];
        float B = sP[4 * ROWS + tid] + sP[5 * ROWS + tid] + sP[6 * ROWS + tid] + sP[7 * ROWS + tid];
        float C = sP[8 * ROWS + tid] + sP[9 * ROWS + tid] + sP[10 * ROWS + tid] + sP[11 * ROWS + tid];
        sCos[tid] = C * rsqrtf(fmaxf(A * B, 1e-30f));
    }
    __syncthreads();
    if (tid == 0) {
        float s = 0.f;
#pragma unroll 8
        for (int i = 0; i < ROWS; i++) s += sCos[i];
        g_loss_part[cta] = s;
        __threadfence();
        int v = atomicAdd(&g_ctr3, 1);
        sLast = (v == NCTA - 1);
    }
    __syncthreads();

    // ---- last CTA: fixed-order final reduction -> scalar loss ----
    if (sLast) {
        __threadfence();
        __shared__ float w[4];
        if (tid < NCTA) {
            float v = g_loss_part[tid];
#pragma unroll
            for (int off = 16; off > 0; off >>= 1)
                v += __shfl_xor_sync(0xffffffffu, v, off);
            if ((tid & 31) == 0) w[tid >> 5] = v;
        }
        __syncthreads();
        if (tid == 0) {
            float s = w[0] + w[1] + w[2] + w[3];
            const float b = (float)BSZ;
            out[0] = (2.f * b - 2.f * s) / (b * b);
        }
    }
}

// ============================================================================
extern "C" void kernel_launch(void* const* d_in, const int* in_sizes, int n_in,
                              void* d_out, int out_size) {
    (void)in_sizes; (void)n_in; (void)out_size;
    const float* zxs = (const float*)d_in[0];
    const float* zys = (const float*)d_in[1];
    const float* zxt = (const float*)d_in[2];
    const float* zyt = (const float*)d_in[3];
    // temperature (d_in[4]) cancels exactly under row-normalization.

    cudaFuncSetAttribute(fused_kernel, cudaFuncAttributeMaxDynamicSharedMemorySize,
                         FUSED_SMEM_BYTES);

    reset_kernel<<<1, 1>>>();
    fused_kernel<<<NCTA, NTHR, FUSED_SMEM_BYTES>>>(zxs, zys, zxt, zyt, (float*)d_out);
}

// round 8
// speedup vs baseline: 1.8128x; 1.1404x over previous
#include <cuda_runtime.h>
#include <cuda_bf16.h>
#include <cstdint>

#define BSZ 8192
#define DIM 128

#define NCTA 128          // one wave: <=148 SMs, 1 CTA/SM (grid-sync safe)
#define ROWS 64           // rows of each tensor per CTA
#define NTHR 512

// shared-memory word (4B) pitches
#define XBP 68            // X bf16 rows: 128 bf16 = 64 words + 4 pad  -> conflict-free
#define YTP 36            // Y^T bf16 rows: 64 bf16 = 32 words + 4 pad -> conflict-free
#define BGP 68            // staged G^T bf16 rows: 64 words + 4 pad

// smem word offsets
#define OFF_XB   0                              // [2][64][XBP]    8704 w
#define OFF_YT   (OFF_XB + 2 * ROWS * XBP)      // [2][128][YTP]   9216 w (reused as bufA)
#define OFF_BUFB (OFF_YT + 2 * DIM * YTP)       // [128][BGP]      8704 w
#define OFF_P    (OFF_BUFB + DIM * BGP)         // [3][4][64]       768 w
#define OFF_COS  (OFF_P + 12 * ROWS)            // [64]
#define SMEM_WORDS (OFF_COS + ROWS)
#define FUSED_SMEM_BYTES (SMEM_WORDS * 4)       // ~110 KB

__device__ float            g_gram_part[NCTA][3][DIM][DIM];  // fp32 partials (~25MB, L2)
__device__ __nv_bfloat16    g_gramT[3][DIM][DIM];            // G^T, bf16
__device__ float            g_loss_part[NCTA];
__device__ int              g_ctr1, g_ctr2, g_ctr3;

// ---------------------------------------------------------------------------
__device__ __forceinline__ void mma_bf16(float* d, const uint32_t* a, uint32_t b0, uint32_t b1) {
    asm volatile(
        "mma.sync.aligned.m16n8k16.row.col.f32.bf16.bf16.f32 "
        "{%0,%1,%2,%3}, {%4,%5,%6,%7}, {%8,%9}, {%0,%1,%2,%3};"
        : "+f"(d[0]), "+f"(d[1]), "+f"(d[2]), "+f"(d[3])
        : "r"(a[0]), "r"(a[1]), "r"(a[2]), "r"(a[3]), "r"(b0), "r"(b1));
}
__device__ __forceinline__ uint32_t smem_u32(const void* p) {
    uint32_t a;
    asm("{ .reg .u64 t; cvta.to.shared.u64 t, %1; cvt.u32.u64 %0, t; }" : "=r"(a) : "l"(p));
    return a;
}
__device__ __forceinline__ void cp16(uint32_t dst, const void* src) {
    asm volatile("cp.async.cg.shared.global [%0], [%1], 16;" :: "r"(dst), "l"(src));
}
#define CP_COMMIT() asm volatile("cp.async.commit_group;" ::: "memory")
#define CP_WAIT(n)  asm volatile("cp.async.wait_group %0;" :: "n"(n) : "memory")

__device__ __forceinline__ void grid_arrive(int* ctr, int tid) {
    __threadfence();
    __syncthreads();
    if (tid == 0) atomicAdd(ctr, 1);
}
__device__ __forceinline__ void grid_spin(int* ctr, int target, int tid) {
    if (tid == 0) {
        while (*(volatile int*)ctr < target) __nanosleep(32);
    }
    __syncthreads();
    __threadfence();
}

// Y^T swizzled word index: row f (feature), word kw (sample pair)
#define YW(f, kw) ((f) * YTP + ((kw) ^ ((((f) >> 4) & 7) << 2)))

__global__ void reset_kernel() { g_ctr1 = 0; g_ctr2 = 0; g_ctr3 = 0; }

// ============================================================================
__global__ void __launch_bounds__(NTHR) fused_kernel(const float* __restrict__ zxs,
                                                     const float* __restrict__ zys,
                                                     const float* __restrict__ zxt,
                                                     const float* __restrict__ zyt,
                                                     float* __restrict__ out) {
    extern __shared__ uint32_t smw[];
    float* sP   = (float*)(smw + OFF_P);
    float* sCos = (float*)(smw + OFF_COS);
    __shared__ int sLast;

    const int tid  = threadIdx.x;
    const int wid  = tid >> 5;
    const int lane = tid & 31;
    const int gid  = lane >> 2;
    const int tg   = lane & 3;
    const int cta  = blockIdx.x;
    const int row0 = cta * ROWS;

    // ---- phase 0: load + normalize Y -> transposed bf16 (swizzled) ----
    {
        int r = tid >> 3, part = tid & 7;
        int rw = r >> 1, rb = r & 1;
#pragma unroll 1
        for (int which = 0; which < 2; which++) {
            const float* src = which ? zyt : zys;
            const float4* s = (const float4*)(src + (size_t)(row0 + r) * DIM) + part * 4;
            float4 v[4];
            float ss = 0.f;
#pragma unroll
            for (int i = 0; i < 4; i++) {
                v[i] = s[i];
                ss += v[i].x * v[i].x + v[i].y * v[i].y + v[i].z * v[i].z + v[i].w * v[i].w;
            }
            ss += __shfl_xor_sync(0xffffffffu, ss, 1);
            ss += __shfl_xor_sync(0xffffffffu, ss, 2);
            ss += __shfl_xor_sync(0xffffffffu, ss, 4);
            float inv = rsqrtf(fmaxf(ss, 1e-24f));
            __nv_bfloat16* yb = (__nv_bfloat16*)(smw + OFF_YT + which * DIM * YTP);
            const float* vf = (const float*)v;
#pragma unroll
            for (int i = 0; i < 16; i++) {
                int f = part * 16 + i;
                int word = f * YTP + (rw ^ (((f >> 4) & 7) << 2));
                yb[word * 2 + rb] = __float2bfloat16(vf[i] * inv);
            }
        }
    }
    __syncthreads();

    // ---- phase 1: gram partials via bf16 mma (K=64, k16/step), tile 32x32 ----
    {
        const int m0q = (wid & 3) * 32;
        const int n0q = (wid >> 2) * 32;
#pragma unroll 1
        for (int m = 0; m < 3; m++) {
            const uint32_t* Ya = smw + OFF_YT + (m == 1 ? DIM * YTP : 0);
            const uint32_t* Yb = smw + OFF_YT + (m == 0 ? 0 : DIM * YTP);
            float acc[8][4];
#pragma unroll
            for (int t = 0; t < 8; t++)
#pragma unroll
                for (int j = 0; j < 4; j++) acc[t][j] = 0.f;

#pragma unroll
            for (int k0h = 0; k0h < 32; k0h += 8) {     // k-step 16 samples = 8 words
                uint32_t a[2][4];
#pragma unroll
                for (int mt = 0; mt < 2; mt++) {
                    int mb = m0q + mt * 16;
                    a[mt][0] = Ya[YW(mb + gid,     k0h + tg)];
                    a[mt][1] = Ya[YW(mb + 8 + gid, k0h + tg)];
                    a[mt][2] = Ya[YW(mb + gid,     k0h + 4 + tg)];
                    a[mt][3] = Ya[YW(mb + 8 + gid, k0h + 4 + tg)];
                }
                uint32_t bs[4][2];
#pragma unroll
                for (int t = 0; t < 4; t++) {
                    int n0 = n0q + t * 8;
                    bs[t][0] = Yb[YW(n0 + gid, k0h + tg)];
                    bs[t][1] = Yb[YW(n0 + gid, k0h + 4 + tg)];
                }
#pragma unroll
                for (int mt = 0; mt < 2; mt++)
#pragma unroll
                    for (int t = 0; t < 4; t++)
                        mma_bf16(acc[mt * 4 + t], a[mt], bs[t][0], bs[t][1]);
            }
            float* dst = &g_gram_part[cta][m][0][0];
#pragma unroll
            for (int mt = 0; mt < 2; mt++) {
                int r1 = m0q + mt * 16 + gid, r2 = r1 + 8;
#pragma unroll
                for (int t = 0; t < 4; t++) {
                    int n0 = n0q + t * 8;
                    *(float2*)(dst + r1 * DIM + n0 + 2 * tg) =
                        make_float2(acc[mt * 4 + t][0], acc[mt * 4 + t][1]);
                    *(float2*)(dst + r2 * DIM + n0 + 2 * tg) =
                        make_float2(acc[mt * 4 + t][2], acc[mt * 4 + t][3]);
                }
            }
        }
    }

    // ---- arrive barrier 1; hide X load (natural layout, bf16 pairs) ----
    grid_arrive(&g_ctr1, tid);
    {
        int r = tid >> 3, part = tid & 7;
#pragma unroll 1
        for (int which = 0; which < 2; which++) {
            const float* src = which ? zxt : zxs;
            const float4* s = (const float4*)(src + (size_t)(row0 + r) * DIM) + part * 4;
            float4 v[4];
            float ss = 0.f;
#pragma unroll
            for (int i = 0; i < 4; i++) {
                v[i] = s[i];
                ss += v[i].x * v[i].x + v[i].y * v[i].y + v[i].z * v[i].z + v[i].w * v[i].w;
            }
            ss += __shfl_xor_sync(0xffffffffu, ss, 1);
            ss += __shfl_xor_sync(0xffffffffu, ss, 2);
            ss += __shfl_xor_sync(0xffffffffu, ss, 4);
            float inv = rsqrtf(fmaxf(ss, 1e-24f));
            uint32_t* xb = smw + OFF_XB + (size_t)(which * ROWS + r) * XBP + part * 8;
            const float* vf = (const float*)v;
#pragma unroll
            for (int i = 0; i < 8; i++) {
                __nv_bfloat162 h = __floats2bfloat162_rn(vf[2 * i] * inv, vf[2 * i + 1] * inv);
                xb[i] = *(uint32_t*)&h;
            }
        }
    }
    grid_spin(&g_ctr1, NCTA, tid);

    // ---- phase 2: reduce G slice (fixed order), write transposed bf16 ----
    if (tid < 384) {
        int e = cta * 384 + tid;
        const float* base = &g_gram_part[0][0][0][0];
        float s = 0.f;
#pragma unroll 16
        for (int p = 0; p < NCTA; p++)
            s += base[(size_t)p * (3 * DIM * DIM) + e];
        int mat = e >> 14, rem = e & 16383, a = rem >> 7, b = rem & 127;
        g_gramT[mat][b][a] = __float2bfloat16(s);
    }
    grid_arrive(&g_ctr2, tid);
    grid_spin(&g_ctr2, NCTA, tid);

    // ---- phase 3: quadratic forms (bf16 mma); cp.async double-buffered G ----
    {
        const uint32_t bA = smem_u32(smw + OFF_YT);      // reuse Y region
        const uint32_t bB = smem_u32(smw + OFF_BUFB);
        auto stage = [&](uint32_t dstb, int mat) {
            const char* gsrc = (const char*)&g_gramT[mat][0][0];
#pragma unroll
            for (int i = 0; i < 4; i++) {
                int idx = tid + i * NTHR;                // 2048 x 16B
                int row = idx >> 4, c = idx & 15;
                cp16(dstb + (uint32_t)(row * BGP * 4 + c * 16), gsrc + idx * 16);
            }
        };
        stage(bA, 0); CP_COMMIT();
        stage(bB, 1); CP_COMMIT();

        const int m0 = (wid & 3) * 16;
        const int nq = wid >> 2;

#pragma unroll 1
        for (int m = 0; m < 3; m++) {
            if (m == 1) { stage(bA, 2); CP_COMMIT(); CP_WAIT(1); }
            else if (m == 0) CP_WAIT(1);
            else CP_WAIT(0);
            __syncthreads();

            const uint32_t* bG = (m == 1) ? (smw + OFF_BUFB) : (smw + OFF_YT);
            const uint32_t* Xa = smw + OFF_XB + (m == 1 ? ROWS * XBP : 0);
            const uint32_t* Xb = smw + OFF_XB + (m == 0 ? 0 : ROWS * XBP);

            float acc[4][4];
#pragma unroll
            for (int t = 0; t < 4; t++)
#pragma unroll
                for (int j = 0; j < 4; j++) acc[t][j] = 0.f;

#pragma unroll 2
            for (int k0h = 0; k0h < 64; k0h += 8) {      // 8 k-steps of 16
                uint32_t a[4];
                a[0] = Xa[(m0 + gid) * XBP + k0h + tg];
                a[1] = Xa[(m0 + 8 + gid) * XBP + k0h + tg];
                a[2] = Xa[(m0 + gid) * XBP + k0h + 4 + tg];
                a[3] = Xa[(m0 + 8 + gid) * XBP + k0h + 4 + tg];
#pragma unroll
                for (int t = 0; t < 4; t++) {
                    int n0 = nq * 32 + t * 8;
                    uint32_t b0 = bG[(n0 + gid) * BGP + k0h + tg];
                    uint32_t b1 = bG[(n0 + gid) * BGP + k0h + 4 + tg];
                    mma_bf16(acc[t], a, b0, b1);
                }
            }

            float p1 = 0.f, p2 = 0.f;
#pragma unroll
            for (int t = 0; t < 4; t++) {
                int n0 = nq * 32 + t * 8;
                uint32_t xw1 = Xb[(m0 + gid) * XBP + (n0 >> 1) + tg];
                uint32_t xw2 = Xb[(m0 + 8 + gid) * XBP + (n0 >> 1) + tg];
                float2 f1 = __bfloat1622float2(*(__nv_bfloat162*)&xw1);
                float2 f2 = __bfloat1622float2(*(__nv_bfloat162*)&xw2);
                p1 += acc[t][0] * f1.x + acc[t][1] * f1.y;
                p2 += acc[t][2] * f2.x + acc[t][3] * f2.y;
            }
            p1 += __shfl_xor_sync(0xffffffffu, p1, 1);
            p1 += __shfl_xor_sync(0xffffffffu, p1, 2);
            p2 += __shfl_xor_sync(0xffffffffu, p2, 1);
            p2 += __shfl_xor_sync(0xffffffffu, p2, 2);
            if (tg == 0) {
                sP[(m * 4 + nq) * ROWS + m0 + gid]     = p1;
                sP[(m * 4 + nq) * ROWS + m0 + 8 + gid] = p2;
            }
            __syncthreads();
        }
    }

    // ---- cosines + per-CTA partial ----
    if (tid < ROWS) {
        float A = sP[0 * ROWS + tid] + sP[1 * ROWS + tid] + sP[2 * ROWS + tid] + sP[3 * ROWS + tid];
        float B = sP[4 * ROWS + tid] + sP[5 * ROWS + tid] + sP[6 * ROWS + tid] + sP[7 * ROWS + tid];
        float C = sP[8 * ROWS + tid] + sP[9 * ROWS + tid] + sP[10 * ROWS + tid] + sP[11 * ROWS + tid];
        sCos[tid] = C * rsqrtf(fmaxf(A * B, 1e-30f));
    }
    __syncthreads();
    if (tid == 0) {
        float s = 0.f;
#pragma unroll 8
        for (int i = 0; i < ROWS; i++) s += sCos[i];
        g_loss_part[cta] = s;
        __threadfence();
        int v = atomicAdd(&g_ctr3, 1);
        sLast = (v == NCTA - 1);
    }
    __syncthreads();

    if (sLast) {
        __threadfence();
        __shared__ float w[4];
        if (tid < NCTA) {
            float v = g_loss_part[tid];
#pragma unroll
            for (int off = 16; off > 0; off >>= 1)
                v += __shfl_xor_sync(0xffffffffu, v, off);
            if ((tid & 31) == 0) w[tid >> 5] = v;
        }
        __syncthreads();
        if (tid == 0) {
            float s = w[0] + w[1] + w[2] + w[3];
            const float b = (float)BSZ;
            out[0] = (2.f * b - 2.f * s) / (b * b);
        }
    }
}

// ============================================================================
extern "C" void kernel_launch(void* const* d_in, const int* in_sizes, int n_in,
                              void* d_out, int out_size) {
    (void)in_sizes; (void)n_in; (void)out_size;
    const float* zxs = (const float*)d_in[0];
    const float* zys = (const float*)d_in[1];
    const float* zxt = (const float*)d_in[2];
    const float* zyt = (const float*)d_in[3];
    // temperature (d_in[4]) cancels exactly under row-normalization.

    cudaFuncSetAttribute(fused_kernel, cudaFuncAttributeMaxDynamicSharedMemorySize,
                         FUSED_SMEM_BYTES);

    reset_kernel<<<1, 1>>>();
    fused_kernel<<<NCTA, NTHR, FUSED_SMEM_BYTES>>>(zxs, zys, zxt, zyt, (float*)d_out);
}

// round 9
// speedup vs baseline: 1.8288x; 1.0088x over previous
#include <cuda_runtime.h>
#include <cuda_bf16.h>
#include <cstdint>

#define BSZ 8192
#define DIM 128

#define NCTA 128          // one wave: <=148 SMs, 1 CTA/SM (grid-sync safe)
#define ROWS 64           // rows of each tensor per CTA
#define NTHR 512

// shared-memory word (4B) pitches
#define XBP 68            // X bf16 rows: 64 words + 4 pad (68%4==0, 16B-aligned rows)
#define YTP 36            // Y^T bf16 rows: 32 words + 4 pad
#define BGP 68            // staged G^T bf16 rows

// smem word offsets
#define OFF_XB   0                              // [2][64][XBP]
#define OFF_YT   (OFF_XB + 2 * ROWS * XBP)      // [2][128][YTP] (reused as bufA)
#define OFF_BUFB (OFF_YT + 2 * DIM * YTP)       // [128][BGP]
#define OFF_P    (OFF_BUFB + DIM * BGP)         // [3][4][64]
#define OFF_COS  (OFF_P + 12 * ROWS)            // [64]
#define SMEM_WORDS (OFF_COS + ROWS)
#define FUSED_SMEM_BYTES (SMEM_WORDS * 4)       // ~110 KB

__device__ uint32_t         g_gram_part_bf[NCTA][3][DIM][DIM / 2]; // bf16x2 partials (~12.6MB)
__device__ __nv_bfloat16    g_gramT[3][DIM][DIM];                  // G^T, bf16
__device__ float            g_loss_part[NCTA];
__device__ int              g_ctr1, g_ctr2, g_ctr3;

// ---------------------------------------------------------------------------
__device__ __forceinline__ void mma_bf16(float* d, const uint32_t* a, uint32_t b0, uint32_t b1) {
    asm volatile(
        "mma.sync.aligned.m16n8k16.row.col.f32.bf16.bf16.f32 "
        "{%0,%1,%2,%3}, {%4,%5,%6,%7}, {%8,%9}, {%0,%1,%2,%3};"
        : "+f"(d[0]), "+f"(d[1]), "+f"(d[2]), "+f"(d[3])
        : "r"(a[0]), "r"(a[1]), "r"(a[2]), "r"(a[3]), "r"(b0), "r"(b1));
}
__device__ __forceinline__ void ldsm_x4(uint32_t* r, uint32_t addr) {
    asm volatile("ldmatrix.sync.aligned.m8n8.x4.shared.b16 {%0,%1,%2,%3}, [%4];"
        : "=r"(r[0]), "=r"(r[1]), "=r"(r[2]), "=r"(r[3]) : "r"(addr));
}
__device__ __forceinline__ uint32_t smem_u32(const void* p) {
    uint32_t a;
    asm("{ .reg .u64 t; cvta.to.shared.u64 t, %1; cvt.u32.u64 %0, t; }" : "=r"(a) : "l"(p));
    return a;
}
__device__ __forceinline__ void cp16(uint32_t dst, const void* src) {
    asm volatile("cp.async.cg.shared.global [%0], [%1], 16;" :: "r"(dst), "l"(src));
}
#define CP_COMMIT() asm volatile("cp.async.commit_group;" ::: "memory")
#define CP_WAIT(n)  asm volatile("cp.async.wait_group %0;" :: "n"(n) : "memory")

__device__ __forceinline__ void grid_arrive(int* ctr, int tid) {
    __threadfence();
    __syncthreads();
    if (tid == 0) atomicAdd(ctr, 1);
}
__device__ __forceinline__ void grid_spin(int* ctr, int target, int tid) {
    if (tid == 0) {
        while (*(volatile int*)ctr < target) __nanosleep(32);
    }
    __syncthreads();
    __threadfence();
}

// Y^T swizzled word index: row f (feature), word kw (sample pair)
#define YW(f, kw) ((f) * YTP + ((kw) ^ ((((f) >> 4) & 7) << 2)))

__global__ void reset_kernel() { g_ctr1 = 0; g_ctr2 = 0; g_ctr3 = 0; }

// ============================================================================
__global__ void __launch_bounds__(NTHR) fused_kernel(const float* __restrict__ zxs,
                                                     const float* __restrict__ zys,
                                                     const float* __restrict__ zxt,
                                                     const float* __restrict__ zyt,
                                                     float* __restrict__ out) {
    extern __shared__ uint32_t smw[];
    float* sP   = (float*)(smw + OFF_P);
    float* sCos = (float*)(smw + OFF_COS);
    __shared__ int sLast;

    const int tid  = threadIdx.x;
    const int wid  = tid >> 5;
    const int lane = tid & 31;
    const int gid  = lane >> 2;
    const int tg   = lane & 3;
    const int fl   = lane & 15;            // ldmatrix row-lane
    const int kh   = (lane >> 4) << 2;     // ldmatrix k-half (0 or 4 words)
    const int cta  = blockIdx.x;
    const int row0 = cta * ROWS;

    // ---- phase 0: load + normalize Y -> transposed bf16 (swizzled) ----
    {
        int r = tid >> 3, part = tid & 7;
        int rw = r >> 1, rb = r & 1;
#pragma unroll 1
        for (int which = 0; which < 2; which++) {
            const float* src = which ? zyt : zys;
            const float4* s = (const float4*)(src + (size_t)(row0 + r) * DIM) + part * 4;
            float4 v[4];
            float ss = 0.f;
#pragma unroll
            for (int i = 0; i < 4; i++) {
                v[i] = s[i];
                ss += v[i].x * v[i].x + v[i].y * v[i].y + v[i].z * v[i].z + v[i].w * v[i].w;
            }
            ss += __shfl_xor_sync(0xffffffffu, ss, 1);
            ss += __shfl_xor_sync(0xffffffffu, ss, 2);
            ss += __shfl_xor_sync(0xffffffffu, ss, 4);
            float inv = rsqrtf(fmaxf(ss, 1e-24f));
            __nv_bfloat16* yb = (__nv_bfloat16*)(smw + OFF_YT + which * DIM * YTP);
            const float* vf = (const float*)v;
#pragma unroll
            for (int i = 0; i < 16; i++) {
                int f = part * 16 + i;
                int word = f * YTP + (rw ^ (((f >> 4) & 7) << 2));
                yb[word * 2 + rb] = __float2bfloat16(vf[i] * inv);
            }
        }
    }
    __syncthreads();

    // ---- phase 1: gram partials via bf16 mma + ldmatrix, warp tile 32x32 ----
    {
        const int m0q = (wid & 3) * 32;
        const int n0q = (wid >> 2) * 32;
        const uint32_t ytb = smem_u32(smw + OFF_YT);
#pragma unroll 1
        for (int m = 0; m < 3; m++) {
            const uint32_t aB = ytb + (m == 1 ? DIM * YTP * 4 : 0);
            const uint32_t bB = ytb + (m == 0 ? 0 : DIM * YTP * 4);
            float acc[8][4];
#pragma unroll
            for (int t = 0; t < 8; t++)
#pragma unroll
                for (int j = 0; j < 4; j++) acc[t][j] = 0.f;

#pragma unroll
            for (int k0h = 0; k0h < 32; k0h += 8) {     // k-step 16 samples = 8 words
                uint32_t A[2][4], B[2][4];
#pragma unroll
                for (int mt = 0; mt < 2; mt++) {
                    int f = m0q + mt * 16 + fl;
                    int sw = ((f >> 4) & 7) << 2;
                    ldsm_x4(A[mt], aB + (uint32_t)(f * YTP + ((k0h + kh) ^ sw)) * 4);
                }
#pragma unroll
                for (int p = 0; p < 2; p++) {
                    int f = n0q + p * 16 + fl;
                    int sw = ((f >> 4) & 7) << 2;
                    ldsm_x4(B[p], bB + (uint32_t)(f * YTP + ((k0h + kh) ^ sw)) * 4);
                }
#pragma unroll
                for (int mt = 0; mt < 2; mt++)
#pragma unroll
                    for (int t = 0; t < 4; t++) {
                        int p = t >> 1, sub = t & 1;
                        mma_bf16(acc[mt * 4 + t], A[mt], B[p][sub], B[p][2 + sub]);
                    }
            }
            // epilogue: pack accumulator n-pairs to bf16x2 partials
            uint32_t* dst = &g_gram_part_bf[cta][m][0][0];
#pragma unroll
            for (int mt = 0; mt < 2; mt++) {
                int r1 = m0q + mt * 16 + gid, r2 = r1 + 8;
#pragma unroll
                for (int t = 0; t < 4; t++) {
                    int cw = ((n0q + t * 8) >> 1) + tg;
                    __nv_bfloat162 h1 = __floats2bfloat162_rn(acc[mt * 4 + t][0], acc[mt * 4 + t][1]);
                    __nv_bfloat162 h2 = __floats2bfloat162_rn(acc[mt * 4 + t][2], acc[mt * 4 + t][3]);
                    dst[r1 * (DIM / 2) + cw] = *(uint32_t*)&h1;
                    dst[r2 * (DIM / 2) + cw] = *(uint32_t*)&h2;
                }
            }
        }
    }

    // ---- arrive barrier 1; hide X load (natural layout, bf16 pairs) ----
    grid_arrive(&g_ctr1, tid);
    {
        int r = tid >> 3, part = tid & 7;
#pragma unroll 1
        for (int which = 0; which < 2; which++) {
            const float* src = which ? zxt : zxs;
            const float4* s = (const float4*)(src + (size_t)(row0 + r) * DIM) + part * 4;
            float4 v[4];
            float ss = 0.f;
#pragma unroll
            for (int i = 0; i < 4; i++) {
                v[i] = s[i];
                ss += v[i].x * v[i].x + v[i].y * v[i].y + v[i].z * v[i].z + v[i].w * v[i].w;
            }
            ss += __shfl_xor_sync(0xffffffffu, ss, 1);
            ss += __shfl_xor_sync(0xffffffffu, ss, 2);
            ss += __shfl_xor_sync(0xffffffffu, ss, 4);
            float inv = rsqrtf(fmaxf(ss, 1e-24f));
            uint32_t* xb = smw + OFF_XB + (size_t)(which * ROWS + r) * XBP + part * 8;
            const float* vf = (const float*)v;
#pragma unroll
            for (int i = 0; i < 8; i++) {
                __nv_bfloat162 h = __floats2bfloat162_rn(vf[2 * i] * inv, vf[2 * i + 1] * inv);
                xb[i] = *(uint32_t*)&h;
            }
        }
    }
    grid_spin(&g_ctr1, NCTA, tid);

    // ---- phase 2: reduce bf16 partials (fixed order, fp32), write G^T bf16 ----
    if (tid < 192) {
        int e = cta * 192 + tid;                  // pair index, 128*192 = 24576 total
        const uint32_t* base = &g_gram_part_bf[0][0][0][0];
        float s0 = 0.f, s1 = 0.f;
#pragma unroll 16
        for (int p = 0; p < NCTA; p++) {
            uint32_t u = base[(size_t)p * (3 * DIM * (DIM / 2)) + e];
            float2 f = __bfloat1622float2(*(__nv_bfloat162*)&u);
            s0 += f.x; s1 += f.y;
        }
        int mat = e >> 13, rem = e & 8191, a = rem >> 6, pw = rem & 63;
        g_gramT[mat][2 * pw][a]     = __float2bfloat16(s0);
        g_gramT[mat][2 * pw + 1][a] = __float2bfloat16(s1);
    }
    grid_arrive(&g_ctr2, tid);
    grid_spin(&g_ctr2, NCTA, tid);

    // ---- phase 3: quadratic forms (bf16 mma + ldmatrix); double-buffered G ----
    {
        const uint32_t bA = smem_u32(smw + OFF_YT);      // reuse Y region
        const uint32_t bB = smem_u32(smw + OFF_BUFB);
        auto stage = [&](uint32_t dstb, int mat) {
            const char* gsrc = (const char*)&g_gramT[mat][0][0];
#pragma unroll
            for (int i = 0; i < 4; i++) {
                int idx = tid + i * NTHR;                // 2048 x 16B
                int row = idx >> 4, c = idx & 15;
                cp16(dstb + (uint32_t)(row * BGP * 4 + c * 16), gsrc + idx * 16);
            }
        };
        stage(bA, 0); CP_COMMIT();
        stage(bB, 1); CP_COMMIT();

        const int m0 = (wid & 3) * 16;
        const int nq = wid >> 2;
        const uint32_t xbb = smem_u32(smw + OFF_XB);

#pragma unroll 1
        for (int m = 0; m < 3; m++) {
            if (m == 1) { stage(bA, 2); CP_COMMIT(); CP_WAIT(1); }
            else if (m == 0) CP_WAIT(1);
            else CP_WAIT(0);
            __syncthreads();

            const uint32_t bGb = (m == 1) ? bB : bA;
            const uint32_t xab = xbb + (m == 1 ? ROWS * XBP * 4 : 0);
            const uint32_t* Xb = smw + OFF_XB + (m == 0 ? 0 : ROWS * XBP);

            float acc[4][4];
#pragma unroll
            for (int t = 0; t < 4; t++)
#pragma unroll
                for (int j = 0; j < 4; j++) acc[t][j] = 0.f;

#pragma unroll 2
            for (int k0h = 0; k0h < 64; k0h += 8) {      // 8 k-steps of 16
                uint32_t A[4], B[2][4];
                ldsm_x4(A, xab + (uint32_t)((m0 + fl) * XBP + k0h + kh) * 4);
#pragma unroll
                for (int p = 0; p < 2; p++) {
                    int f = nq * 32 + p * 16 + fl;
                    ldsm_x4(B[p], bGb + (uint32_t)(f * BGP + k0h + kh) * 4);
                }
#pragma unroll
                for (int t = 0; t < 4; t++) {
                    int p = t >> 1, sub = t & 1;
                    mma_bf16(acc[t], A, B[p][sub], B[p][2 + sub]);
                }
            }

            float p1 = 0.f, p2 = 0.f;
#pragma unroll
            for (int t = 0; t < 4; t++) {
                int n0 = nq * 32 + t * 8;
                uint32_t xw1 = Xb[(m0 + gid) * XBP + (n0 >> 1) + tg];
                uint32_t xw2 = Xb[(m0 + 8 + gid) * XBP + (n0 >> 1) + tg];
                float2 f1 = __bfloat1622float2(*(__nv_bfloat162*)&xw1);
                float2 f2 = __bfloat1622float2(*(__nv_bfloat162*)&xw2);
                p1 += acc[t][0] * f1.x + acc[t][1] * f1.y;
                p2 += acc[t][2] * f2.x + acc[t][3] * f2.y;
            }
            p1 += __shfl_xor_sync(0xffffffffu, p1, 1);
            p1 += __shfl_xor_sync(0xffffffffu, p1, 2);
            p2 += __shfl_xor_sync(0xffffffffu, p2, 1);
            p2 += __shfl_xor_sync(0xffffffffu, p2, 2);
            if (tg == 0) {
                sP[(m * 4 + nq) * ROWS + m0 + gid]     = p1;
                sP[(m * 4 + nq) * ROWS + m0 + 8 + gid] = p2;
            }
            __syncthreads();
        }
    }

    // ---- cosines + per-CTA partial ----
    if (tid < ROWS) {
        float A = sP[0 * ROWS + tid] + sP[1 * ROWS + tid] + sP[2 * ROWS + tid] + sP[3 * ROWS + tid];
        float B = sP[4 * ROWS + tid] + sP[5 * ROWS + tid] + sP[6 * ROWS + tid] + sP[7 * ROWS + tid];
        float C = sP[8 * ROWS + tid] + sP[9 * ROWS + tid] + sP[10 * ROWS + tid] + sP[11 * ROWS + tid];
        sCos[tid] = C * rsqrtf(fmaxf(A * B, 1e-30f));
    }
    __syncthreads();
    if (tid == 0) {
        float s = 0.f;
#pragma unroll 8
        for (int i = 0; i < ROWS; i++) s += sCos[i];
        g_loss_part[cta] = s;
        __threadfence();
        int v = atomicAdd(&g_ctr3, 1);
        sLast = (v == NCTA - 1);
    }
    __syncthreads();

    if (sLast) {
        __threadfence();
        __shared__ float w[4];
        if (tid < NCTA) {
            float v = g_loss_part[tid];
#pragma unroll
            for (int off = 16; off > 0; off >>= 1)
                v += __shfl_xor_sync(0xffffffffu, v, off);
            if ((tid & 31) == 0) w[tid >> 5] = v;
        }
        __syncthreads();
        if (tid == 0) {
            float s = w[0] + w[1] + w[2] + w[3];
            const float b = (float)BSZ;
            out[0] = (2.f * b - 2.f * s) / (b * b);
        }
    }
}

// ============================================================================
extern "C" void kernel_launch(void* const* d_in, const int* in_sizes, int n_in,
                              void* d_out, int out_size) {
    (void)in_sizes; (void)n_in; (void)out_size;
    const float* zxs = (const float*)d_in[0];
    const float* zys = (const float*)d_in[1];
    const float* zxt = (const float*)d_in[2];
    const float* zyt = (const float*)d_in[3];
    // temperature (d_in[4]) cancels exactly under row-normalization.

    cudaFuncSetAttribute(fused_kernel, cudaFuncAttributeMaxDynamicSharedMemorySize,
                         FUSED_SMEM_BYTES);

    reset_kernel<<<1, 1>>>();
    fused_kernel<<<NCTA, NTHR, FUSED_SMEM_BYTES>>>(zxs, zys, zxt, zyt, (float*)d_out);
}

// round 10
// speedup vs baseline: 1.9485x; 1.0655x over previous
#include <cuda_runtime.h>
#include <cuda_bf16.h>
#include <cstdint>

#define BSZ 8192
#define DIM 128

#define NCTA 128          // one wave: <=148 SMs, 1 CTA/SM (grid-sync safe)
#define ROWS 64           // rows of each tensor per CTA
#define NTHR 512

// shared-memory word (4B) pitches
#define XBP 68            // X bf16 rows: 64 words + 4 pad (rows 16B-aligned)
#define YTP 36            // Y^T bf16 rows: 32 words + 4 pad
#define BGP 68            // staged G^T bf16 rows

// smem word offsets
#define OFF_XB   0                              // [2][64][XBP] = 8704 w
#define OFF_G    (OFF_XB + 2 * ROWS * XBP)      // [3][128][BGP] = 26112 w (Y^T lives here in phases 0-1)
#define OFF_P    (OFF_G + 3 * DIM * BGP)        // [12][64] = 768 w (also phase-2 sRed)
#define OFF_COS  (OFF_P + 12 * ROWS)            // [64]
#define SMEM_WORDS (OFF_COS + ROWS)
#define FUSED_SMEM_BYTES (SMEM_WORDS * 4)       // ~143 KB

__device__ uint32_t         g_gram_part_bf[NCTA][3][DIM][DIM / 2]; // bf16x2 partials
__device__ __nv_bfloat16    g_gramT[3][DIM][DIM];                  // G^T, bf16
__device__ float            g_loss_part[NCTA];
__device__ int              g_ctr1, g_ctr2, g_ctr3;                // zero-init; last CTA resets

// ---------------------------------------------------------------------------
__device__ __forceinline__ void mma_bf16(float* d, const uint32_t* a, uint32_t b0, uint32_t b1) {
    asm volatile(
        "mma.sync.aligned.m16n8k16.row.col.f32.bf16.bf16.f32 "
        "{%0,%1,%2,%3}, {%4,%5,%6,%7}, {%8,%9}, {%0,%1,%2,%3};"
        : "+f"(d[0]), "+f"(d[1]), "+f"(d[2]), "+f"(d[3])
        : "r"(a[0]), "r"(a[1]), "r"(a[2]), "r"(a[3]), "r"(b0), "r"(b1));
}
__device__ __forceinline__ void ldsm_x4(uint32_t* r, uint32_t addr) {
    asm volatile("ldmatrix.sync.aligned.m8n8.x4.shared.b16 {%0,%1,%2,%3}, [%4];"
        : "=r"(r[0]), "=r"(r[1]), "=r"(r[2]), "=r"(r[3]) : "r"(addr));
}
__device__ __forceinline__ uint32_t smem_u32(const void* p) {
    uint32_t a;
    asm("{ .reg .u64 t; cvta.to.shared.u64 t, %1; cvt.u32.u64 %0, t; }" : "=r"(a) : "l"(p));
    return a;
}
__device__ __forceinline__ void cp16(uint32_t dst, const void* src) {
    asm volatile("cp.async.cg.shared.global [%0], [%1], 16;" :: "r"(dst), "l"(src));
}
#define CP_COMMIT() asm volatile("cp.async.commit_group;" ::: "memory")
#define CP_WAIT(n)  asm volatile("cp.async.wait_group %0;" :: "n"(n) : "memory")

__device__ __forceinline__ void grid_arrive(int* ctr, int tid) {
    __threadfence();
    __syncthreads();
    if (tid == 0) atomicAdd(ctr, 1);
}
__device__ __forceinline__ void grid_spin(int* ctr, int target, int tid) {
    if (tid == 0) {
        while (*(volatile int*)ctr < target) __nanosleep(32);
    }
    __syncthreads();
    __threadfence();
}

// ============================================================================
__global__ void __launch_bounds__(NTHR) fused_kernel(const float* __restrict__ zxs,
                                                     const float* __restrict__ zys,
                                                     const float* __restrict__ zxt,
                                                     const float* __restrict__ zyt,
                                                     float* __restrict__ out) {
    extern __shared__ uint32_t smw[];
    float* sP   = (float*)(smw + OFF_P);     // phase-2 sRed, then phase-3 partials
    float* sCos = (float*)(smw + OFF_COS);
    __shared__ int sLast;

    const int tid  = threadIdx.x;
    const int wid  = tid >> 5;
    const int lane = tid & 31;
    const int gid  = lane >> 2;
    const int tg   = lane & 3;
    const int fl   = lane & 15;            // ldmatrix row-lane
    const int kh   = (lane >> 4) << 2;     // ldmatrix k-half (0 or 4 words)
    const int cta  = blockIdx.x;
    const int row0 = cta * ROWS;

    // ---- phase 0: load + normalize Y -> transposed bf16 (swizzled) ----
    {
        int r = tid >> 3, part = tid & 7;
        int rw = r >> 1, rb = r & 1;
#pragma unroll 1
        for (int which = 0; which < 2; which++) {
            const float* src = which ? zyt : zys;
            const float4* s = (const float4*)(src + (size_t)(row0 + r) * DIM) + part * 4;
            float4 v[4];
            float ss = 0.f;
#pragma unroll
            for (int i = 0; i < 4; i++) {
                v[i] = s[i];
                ss += v[i].x * v[i].x + v[i].y * v[i].y + v[i].z * v[i].z + v[i].w * v[i].w;
            }
            ss += __shfl_xor_sync(0xffffffffu, ss, 1);
            ss += __shfl_xor_sync(0xffffffffu, ss, 2);
            ss += __shfl_xor_sync(0xffffffffu, ss, 4);
            float inv = rsqrtf(fmaxf(ss, 1e-24f));
            __nv_bfloat16* yb = (__nv_bfloat16*)(smw + OFF_G + which * DIM * YTP);
            const float* vf = (const float*)v;
#pragma unroll
            for (int i = 0; i < 16; i++) {
                int f = part * 16 + i;
                int word = f * YTP + (rw ^ (((f >> 4) & 7) << 2));
                yb[word * 2 + rb] = __float2bfloat16(vf[i] * inv);
            }
        }
    }
    __syncthreads();

    // ---- phase 1: gram partials via bf16 mma + ldmatrix, warp tile 32x32 ----
    {
        const int m0q = (wid & 3) * 32;
        const int n0q = (wid >> 2) * 32;
        const uint32_t ytb = smem_u32(smw + OFF_G);
#pragma unroll 1
        for (int m = 0; m < 3; m++) {
            const uint32_t aB = ytb + (m == 1 ? DIM * YTP * 4 : 0);
            const uint32_t bB = ytb + (m == 0 ? 0 : DIM * YTP * 4);
            float acc[8][4];
#pragma unroll
            for (int t = 0; t < 8; t++)
#pragma unroll
                for (int j = 0; j < 4; j++) acc[t][j] = 0.f;

#pragma unroll
            for (int k0h = 0; k0h < 32; k0h += 8) {     // k-step 16 samples = 8 words
                uint32_t A[2][4], B[2][4];
#pragma unroll
                for (int mt = 0; mt < 2; mt++) {
                    int f = m0q + mt * 16 + fl;
                    int sw = ((f >> 4) & 7) << 2;
                    ldsm_x4(A[mt], aB + (uint32_t)(f * YTP + ((k0h + kh) ^ sw)) * 4);
                }
#pragma unroll
                for (int p = 0; p < 2; p++) {
                    int f = n0q + p * 16 + fl;
                    int sw = ((f >> 4) & 7) << 2;
                    ldsm_x4(B[p], bB + (uint32_t)(f * YTP + ((k0h + kh) ^ sw)) * 4);
                }
#pragma unroll
                for (int mt = 0; mt < 2; mt++)
#pragma unroll
                    for (int t = 0; t < 4; t++) {
                        int p = t >> 1, sub = t & 1;
                        mma_bf16(acc[mt * 4 + t], A[mt], B[p][sub], B[p][2 + sub]);
                    }
            }
            uint32_t* dst = &g_gram_part_bf[cta][m][0][0];
#pragma unroll
            for (int mt = 0; mt < 2; mt++) {
                int r1 = m0q + mt * 16 + gid, r2 = r1 + 8;
#pragma unroll
                for (int t = 0; t < 4; t++) {
                    int cw = ((n0q + t * 8) >> 1) + tg;
                    __nv_bfloat162 h1 = __floats2bfloat162_rn(acc[mt * 4 + t][0], acc[mt * 4 + t][1]);
                    __nv_bfloat162 h2 = __floats2bfloat162_rn(acc[mt * 4 + t][2], acc[mt * 4 + t][3]);
                    dst[r1 * (DIM / 2) + cw] = *(uint32_t*)&h1;
                    dst[r2 * (DIM / 2) + cw] = *(uint32_t*)&h2;
                }
            }
        }
    }

    // ---- arrive barrier 1; hide X load (natural layout, bf16 pairs) ----
    grid_arrive(&g_ctr1, tid);
    {
        int r = tid >> 3, part = tid & 7;
#pragma unroll 1
        for (int which = 0; which < 2; which++) {
            const float* src = which ? zxt : zxs;
            const float4* s = (const float4*)(src + (size_t)(row0 + r) * DIM) + part * 4;
            float4 v[4];
            float ss = 0.f;
#pragma unroll
            for (int i = 0; i < 4; i++) {
                v[i] = s[i];
                ss += v[i].x * v[i].x + v[i].y * v[i].y + v[i].z * v[i].z + v[i].w * v[i].w;
            }
            ss += __shfl_xor_sync(0xffffffffu, ss, 1);
            ss += __shfl_xor_sync(0xffffffffu, ss, 2);
            ss += __shfl_xor_sync(0xffffffffu, ss, 4);
            float inv = rsqrtf(fmaxf(ss, 1e-24f));
            uint32_t* xb = smw + OFF_XB + (size_t)(which * ROWS + r) * XBP + part * 8;
            const float* vf = (const float*)v;
#pragma unroll
            for (int i = 0; i < 8; i++) {
                __nv_bfloat162 h = __floats2bfloat162_rn(vf[2 * i] * inv, vf[2 * i + 1] * inv);
                xb[i] = *(uint32_t*)&h;
            }
        }
    }
    grid_spin(&g_ctr1, NCTA, tid);

    // ---- phase 2: reduce bf16 partials, 2-way split over partials ----
    // threads 0-383: half = tid/192 sums partials [half*64, half*64+64)
    {
        float s0 = 0.f, s1 = 0.f;
        int t192 = tid % 192;
        int half = tid / 192;
        if (tid < 384) {
            int e = cta * 192 + t192;
            const uint32_t* base = &g_gram_part_bf[0][0][0][0] + (size_t)(half * 64) * (3 * DIM * (DIM / 2));
#pragma unroll 16
            for (int p = 0; p < 64; p++) {
                uint32_t u = base[(size_t)p * (3 * DIM * (DIM / 2)) + e];
                float2 f = __bfloat1622float2(*(__nv_bfloat162*)&u);
                s0 += f.x; s1 += f.y;
            }
            sP[(half * 192 + t192) * 2]     = s0;
            sP[(half * 192 + t192) * 2 + 1] = s1;
        }
        __syncthreads();
        if (tid < 192) {
            int e = cta * 192 + tid;
            float a0 = sP[tid * 2]     + sP[(192 + tid) * 2];
            float a1 = sP[tid * 2 + 1] + sP[(192 + tid) * 2 + 1];
            int mat = e >> 13, rem = e & 8191, a = rem >> 6, pw = rem & 63;
            g_gramT[mat][2 * pw][a]     = __float2bfloat16(a0);
            g_gramT[mat][2 * pw + 1][a] = __float2bfloat16(a1);
        }
    }
    grid_arrive(&g_ctr2, tid);
    grid_spin(&g_ctr2, NCTA, tid);

    // ---- phase 3: stage ALL 3 G mats at once; quad forms, no intra-loop syncs
    {
        const uint32_t gb = smem_u32(smw + OFF_G);
        {
            const char* gsrc = (const char*)&g_gramT[0][0][0];
#pragma unroll
            for (int i = 0; i < 12; i++) {
                int idx = tid + i * NTHR;               // 6144 x 16B
                int mat = idx >> 11;
                int rem = idx & 2047;
                int row = rem >> 4, c = rem & 15;
                cp16(gb + (uint32_t)((mat * DIM + row) * BGP * 4 + c * 16), gsrc + idx * 16);
            }
        }
        CP_COMMIT();
        CP_WAIT(0);
        __syncthreads();

        const int m0 = (wid & 3) * 16;
        const int nq = wid >> 2;
        const uint32_t xbb = smem_u32(smw + OFF_XB);

#pragma unroll 1
        for (int m = 0; m < 3; m++) {
            const uint32_t bGb = gb + (uint32_t)(m * DIM * BGP) * 4;
            const uint32_t xab = xbb + (m == 1 ? ROWS * XBP * 4 : 0);
            const uint32_t* Xb = smw + OFF_XB + (m == 0 ? 0 : ROWS * XBP);

            float acc[4][4];
#pragma unroll
            for (int t = 0; t < 4; t++)
#pragma unroll
                for (int j = 0; j < 4; j++) acc[t][j] = 0.f;

#pragma unroll 2
            for (int k0h = 0; k0h < 64; k0h += 8) {      // 8 k-steps of 16
                uint32_t A[4], B[2][4];
                ldsm_x4(A, xab + (uint32_t)((m0 + fl) * XBP + k0h + kh) * 4);
#pragma unroll
                for (int p = 0; p < 2; p++) {
                    int f = nq * 32 + p * 16 + fl;
                    ldsm_x4(B[p], bGb + (uint32_t)(f * BGP + k0h + kh) * 4);
                }
#pragma unroll
                for (int t = 0; t < 4; t++) {
                    int p = t >> 1, sub = t & 1;
                    mma_bf16(acc[t], A, B[p][sub], B[p][2 + sub]);
                }
            }

            float p1 = 0.f, p2 = 0.f;
#pragma unroll
            for (int t = 0; t < 4; t++) {
                int n0 = nq * 32 + t * 8;
                uint32_t xw1 = Xb[(m0 + gid) * XBP + (n0 >> 1) + tg];
                uint32_t xw2 = Xb[(m0 + 8 + gid) * XBP + (n0 >> 1) + tg];
                float2 f1 = __bfloat1622float2(*(__nv_bfloat162*)&xw1);
                float2 f2 = __bfloat1622float2(*(__nv_bfloat162*)&xw2);
                p1 += acc[t][0] * f1.x + acc[t][1] * f1.y;
                p2 += acc[t][2] * f2.x + acc[t][3] * f2.y;
            }
            p1 += __shfl_xor_sync(0xffffffffu, p1, 1);
            p1 += __shfl_xor_sync(0xffffffffu, p1, 2);
            p2 += __shfl_xor_sync(0xffffffffu, p2, 1);
            p2 += __shfl_xor_sync(0xffffffffu, p2, 2);
            if (tg == 0) {
                sP[(m * 4 + nq) * ROWS + m0 + gid]     = p1;
                sP[(m * 4 + nq) * ROWS + m0 + 8 + gid] = p2;
            }
        }
    }
    __syncthreads();

    // ---- cosines + per-CTA partial ----
    if (tid < ROWS) {
        float A = sP[0 * ROWS + tid] + sP[1 * ROWS + tid] + sP[2 * ROWS + tid] + sP[3 * ROWS + tid];
        float B = sP[4 * ROWS + tid] + sP[5 * ROWS + tid] + sP[6 * ROWS + tid] + sP[7 * ROWS + tid];
        float C = sP[8 * ROWS + tid] + sP[9 * ROWS + tid] + sP[10 * ROWS + tid] + sP[11 * ROWS + tid];
        sCos[tid] = C * rsqrtf(fmaxf(A * B, 1e-30f));
    }
    __syncthreads();
    if (tid == 0) {
        float s = 0.f;
#pragma unroll 8
        for (int i = 0; i < ROWS; i++) s += sCos[i];
        g_loss_part[cta] = s;
        __threadfence();
        int v = atomicAdd(&g_ctr3, 1);
        sLast = (v == NCTA - 1);
    }
    __syncthreads();

    // ---- last CTA: final reduction, write loss, reset counters for next run
    if (sLast) {
        __threadfence();
        __shared__ float w[4];
        if (tid < NCTA) {
            float v = g_loss_part[tid];
#pragma unroll
            for (int off = 16; off > 0; off >>= 1)
                v += __shfl_xor_sync(0xffffffffu, v, off);
            if ((tid & 31) == 0) w[tid >> 5] = v;
        }
        __syncthreads();
        if (tid == 0) {
            float s = w[0] + w[1] + w[2] + w[3];
            const float b = (float)BSZ;
            out[0] = (2.f * b - 2.f * s) / (b * b);
            // reset for next launch (stream order guarantees visibility)
            g_ctr1 = 0; g_ctr2 = 0; g_ctr3 = 0;
            __threadfence();
        }
    }
}

// ============================================================================
extern "C" void kernel_launch(void* const* d_in, const int* in_sizes, int n_in,
                              void* d_out, int out_size) {
    (void)in_sizes; (void)n_in; (void)out_size;
    const float* zxs = (const float*)d_in[0];
    const float* zys = (const float*)d_in[1];
    const float* zxt = (const float*)d_in[2];
    const float* zyt = (const float*)d_in[3];
    // temperature (d_in[4]) cancels exactly under row-normalization.

    cudaFuncSetAttribute(fused_kernel, cudaFuncAttributeMaxDynamicSharedMemorySize,
                         FUSED_SMEM_BYTES);

    fused_kernel<<<NCTA, NTHR, FUSED_SMEM_BYTES>>>(zxs, zys, zxt, zyt, (float*)d_out);
}